// round 6
// baseline (speedup 1.0000x reference)
#include <cuda_runtime.h>
#include <cstdint>
#include <type_traits>

namespace plp {

constexpr int NBINS   = 257;
constexpr int N_CH    = 40;
constexpr int ORDER   = 16;
constexpr int RPW     = 32;                 // rows per warp (lane = row)
constexpr int WARP_FLOATS = RPW * NBINS;    // 8224
constexpr int CB      = 16;                 // bins per chunk
constexpr int NCHUNK  = 16;                 // 16*16 = bins 0..255 staged
constexpr int STAGES  = 3;
constexpr int SROW    = 20;                 // 80B: 16B-aligned + LDS.128 conflict-free
constexpr int STAGE_FLOATS = RPW * SROW;    // 640
constexpr int WPB     = 4;
constexpr int BLOCK   = WPB * 32;

// ---------------- compile-time double-precision math ----------------
constexpr double cexp(double x) {
    double s = 1.0, t = 1.0;
    for (int k = 1; k < 60; ++k) { t = t * x / k; s += t; }
    return s;
}
constexpr double cln(double x) {
    int n = 0;
    while (x > 1.3333333333333333) { x *= 0.5; ++n; }
    while (x < 0.75)               { x *= 2.0; --n; }
    double t = (x - 1.0) / (x + 1.0), t2 = t * t, s = 0.0, p = t;
    for (int k = 0; k < 40; ++k) { s += p / (2 * k + 1); p *= t2; }
    return 2.0 * s + n * 0.69314718055994530941723212145818;
}
constexpr double ccos(double x) {
    while (x >  3.14159265358979323846) x -= 6.28318530717958647692528676656;
    while (x < -3.14159265358979323846) x += 6.28318530717958647692528676656;
    double x2 = x * x, s = 1.0, t = 1.0;
    for (int k = 1; k < 30; ++k) { t *= -x2 / ((2.0 * k - 1.0) * (2.0 * k)); s += t; }
    return s;
}
constexpr double csin(double x) {
    double x2 = x * x, s = x, t = x;
    for (int k = 1; k < 30; ++k) { t *= -x2 / ((2.0 * k) * (2.0 * k + 1.0)); s += t; }
    return s;
}

// ---------------- all problem constants, built at compile time ----------------
struct Tables {
    int   chlo[256]; float wlo[256];
    int   chhi[256]; float whi[256];
    float eql[N_CH];
    float Cp[20][ORDER + 1];   // paired cosine coeffs (q=1..20), edges folded into q=1
    float lift[ORDER];
};

constexpr Tables build() {
    Tables T{};
    const double mel_max = 1127.0 * cln(1.0 + 8000.0 / 700.0);
    const double d = mel_max / 41.0;
    double cf[41]{};   for (int s = 0; s < 41; ++s) cf[s] = d * (s + 1);
    double diff[41]{}; diff[0] = cf[0];
    for (int i = 1; i < 41; ++i) diff[i] = cf[i] - cf[i - 1];

    for (int b = 1; b < 256; ++b) {
        const double mel = 1127.0 * cln(1.0 + (31.25 * b) / 700.0);
        int ch = 0;
        for (int s = 0; s < 41; ++s) if (cf[s] < mel) ++ch;   // searchsorted 'left'
        const double w = (cf[ch] - mel) / diff[ch];
        T.chlo[b] = ch - 1;                 T.wlo[b] = (float)w;
        T.chhi[b] = (ch <= 39) ? ch : -1;   T.whi[b] = (float)(1.0 - w);
    }
    T.chlo[0] = -1; T.chhi[0] = -1;
    for (int c = 0; c < N_CH; ++c) {
        const double fhz = 700.0 * (cexp(cf[c] / 1127.0) - 1.0);
        const double f2  = fhz * fhz;
        T.eql[c] = (float)((f2 / (f2 + 160000.0)) * (f2 / (f2 + 160000.0))
                           * (f2 + 1440000.0) / (f2 + 9610000.0));
    }
    // paired cosine transform:
    // r[k] = sum_{q=1..20} Cp[q-1][k] * (k even ? y[q-1]+y[40-q] : y[q-1]-y[40-q])
    for (int q = 1; q <= 20; ++q)
        for (int k = 0; k <= ORDER; ++k) {
            double v = 2.0 * ccos(6.28318530717958647692528676656
                                  * (double)(q * k) / 82.0) / 82.0;
            if (q == 1) v += 1.0 / 82.0;
            T.Cp[q - 1][k] = (float)v;
        }
    for (int m = 1; m <= ORDER; ++m)
        T.lift[m - 1] = (float)(1.0 + 11.0 * csin(3.14159265358979323846 * m / 22.0));
    return T;
}
constexpr Tables TB = build();

// ---------------- compile-time for-loop ----------------
template <int I, int N> struct SF {
    template <class F>
    __device__ __forceinline__ static void run(F&& f) {
        f(std::integral_constant<int, I>{});
        SF<I + 1, N>::run((F&&)f);
    }
};
template <int N> struct SF<N, N> {
    template <class F> __device__ __forceinline__ static void run(F&&) {}
};

__device__ __forceinline__ void cpa4(unsigned dst, const float* src) {
    asm volatile("cp.async.ca.shared.global [%0], [%1], 4;\n" :: "r"(dst), "l"(src));
}
__device__ __forceinline__ void cpa_commit() {
    asm volatile("cp.async.commit_group;\n" ::: "memory");
}
template <int N>
__device__ __forceinline__ void cpa_wait() {
    asm volatile("cp.async.wait_group %0;\n" :: "n"(N) : "memory");
}

__global__ void __launch_bounds__(BLOCK, 7)
plp_kernel(const float* __restrict__ x, float* __restrict__ out, int nWarpsTotal) {
    __shared__ float sbuf[WPB][STAGES][STAGE_FLOATS];   // 4*3*2560B = 30720B

    const int lane = threadIdx.x & 31;
    const int wInB = threadIdx.x >> 5;
    const int warpG = blockIdx.x * WPB + wInB;
    if (warpG >= nWarpsTotal) return;

    const float* gw = x + (long long)warpG * WARP_FLOATS;

    const unsigned sb =
        (unsigned)__cvta_generic_to_shared(&sbuf[wInB][0][0]);

    // per-lane constant parts of the cp.async src/dst addressing:
    // instr t of a chunk covers rows 2t (lanes 0..15) and 2t+1 (lanes 16..31)
    const int half = lane >> 4;                 // 0/1
    const int colv = lane & 15;                 // column within chunk
    const float* gp = gw + half * NBINS + colv; // + c*CB + t*2*NBINS
    const unsigned hc = (unsigned)((half * SROW + colv) * 4);

    auto issue_chunk = [&](int c, int stg) {
        const unsigned dstBase = sb + (unsigned)(stg * STAGE_FLOATS * 4) + hc;
        const float* srcBase = gp + c * CB;
        SF<0, RPW / 2>::run([&](auto tc) {
            constexpr int t = tc.value;
            cpa4(dstBase + t * (2 * SROW * 4), srcBase + t * (2 * NBINS));
        });
        cpa_commit();
    };

    float fb[N_CH];
    SF<0, N_CH>::run([&](auto c) { fb[c.value] = 0.f; });

    // ---- prologue: 2 chunks in flight ----
    issue_chunk(0, 0);
    issue_chunk(1, 1);

    // ---- 16 chunks of 16 bins, 3-stage ring, lookahead 2, LDS.128 consume ----
    SF<0, NCHUNK>::run([&](auto cc) {
        constexpr int c = cc.value;
        if constexpr (c + 2 < NCHUNK) issue_chunk(c + 2, (c + 2) % STAGES);
        if constexpr (c + 2 < NCHUNK)      cpa_wait<2>();
        else if constexpr (c + 1 < NCHUNK) cpa_wait<1>();
        else                               cpa_wait<0>();
        __syncwarp();
        // vectorized read of this lane's 16 bins: 4x LDS.128, conflict-free
        const float4* xr4 = reinterpret_cast<const float4*>(
            &sbuf[wInB][c % STAGES][lane * SROW]);
        float xv[CB];
        SF<0, CB / 4>::run([&](auto vc) {
            constexpr int v = vc.value;
            const float4 q = xr4[v];
            xv[4 * v + 0] = q.x; xv[4 * v + 1] = q.y;
            xv[4 * v + 2] = q.z; xv[4 * v + 3] = q.w;
        });
        SF<0, CB>::run([&](auto jc) {
            constexpr int j = jc.value;
            constexpr int b = CB * c + j;
            constexpr int clo = TB.chlo[b];
            constexpr int chi = TB.chhi[b];
            if constexpr (clo >= 0) { constexpr float w = TB.wlo[b]; fb[clo] = fmaf(w, xv[j], fb[clo]); }
            if constexpr (chi >= 0) { constexpr float w = TB.whi[b]; fb[chi] = fmaf(w, xv[j], fb[chi]); }
        });
        __syncwarp();   // all lanes done reading before this stage is overwritten
    });

    // ---- equal-loudness + compression (MUFU) ----
    float y[N_CH];
    SF<0, N_CH>::run([&](auto cc_) {
        constexpr int c = cc_.value;
        constexpr float e = TB.eql[c];
        const float v = fmaxf(fb[c], 1e-5f) * e;
        y[c] = __expf(0.33f * __logf(v));
    });

    // ---- autocorrelation via parity-folded cosine transform ----
    float sp[20], sm[20];
    SF<0, 20>::run([&](auto qc) {
        constexpr int q = qc.value;
        sp[q] = y[q] + y[39 - q];
        sm[q] = y[q] - y[39 - q];
    });
    float r[ORDER + 1];
    SF<0, ORDER + 1>::run([&](auto kc) { r[kc.value] = 0.f; });
    SF<0, 20>::run([&](auto qc) {
        constexpr int q = qc.value;
        const float vp = sp[q], vm = sm[q];
        SF<0, ORDER + 1>::run([&](auto kc) {
            constexpr int k = kc.value;
            constexpr float cqk = TB.Cp[q][k];
            r[k] = fmaf(cqk, (k & 1) ? vm : vp, r[k]);
        });
    });

    // ---- Levinson-Durbin (order 16) ----
    float A[ORDER];
    float E = r[0];
    #pragma unroll
    for (int i = 1; i <= ORDER; ++i) {
        float acc = r[i];
        #pragma unroll
        for (int j = 1; j < i; ++j) acc += A[j - 1] * r[i - j];
        const float kk = -__fdividef(acc, E);
        #pragma unroll
        for (int j = 0; j < (i - 1) / 2; ++j) {
            const float t = A[j];
            A[j]         = t + kk * A[i - 2 - j];
            A[i - 2 - j] = A[i - 2 - j] + kk * t;
        }
        if (((i - 1) & 1) == 1) {
            const int mid = (i - 2) / 2;
            A[mid] = A[mid] + kk * A[mid];
        }
        A[i - 1] = kk;
        E = E * (1.0f - kk * kk);
    }

    // ---- LPC -> cepstrum ----
    float cst[ORDER + 1];
    cst[0] = 0.5f * __logf(E);
    #pragma unroll
    for (int m = 1; m <= ORDER; ++m) {
        float acc = A[m - 1];
        #pragma unroll
        for (int k2 = 1; k2 < m; ++k2) {
            const float ratio = (float)k2 / (float)m;
            acc += ratio * cst[k2] * A[m - k2 - 1];
        }
        cst[m] = -acc;
    }

    // ---- lifter + store ----
    float o[ORDER];
    SF<0, ORDER>::run([&](auto ic) {
        constexpr int i = ic.value;
        constexpr float lf = TB.lift[i];
        o[i] = cst[i + 1] * lf;
    });

    const long long row = (long long)warpG * RPW + lane;
    float4* o4 = reinterpret_cast<float4*>(out + row * 16);
    o4[0] = make_float4(o[0],  o[1],  o[2],  o[3]);
    o4[1] = make_float4(o[4],  o[5],  o[6],  o[7]);
    o4[2] = make_float4(o[8],  o[9],  o[10], o[11]);
    o4[3] = make_float4(o[12], o[13], o[14], o[15]);
}

} // namespace plp

extern "C" void kernel_launch(void* const* d_in, const int* in_sizes, int n_in,
                              void* d_out, int out_size) {
    const float* x = (const float*)d_in[0];
    float* out = (float*)d_out;

    const int rows   = in_sizes[0] / plp::NBINS;     // 131072
    const int nWarps = rows / plp::RPW;              // 4096
    const int grid   = (nWarps + plp::WPB - 1) / plp::WPB;  // 1024

    plp::plp_kernel<<<grid, plp::BLOCK>>>(x, out, nWarps);
}

// round 7
// speedup vs baseline: 1.5991x; 1.5991x over previous
#include <cuda_runtime.h>
#include <cstdint>
#include <type_traits>

namespace plp {

constexpr int NBINS   = 257;
constexpr int N_CH    = 40;
constexpr int ORDER   = 16;
constexpr int RPW     = 32;                 // rows per warp (lane = row)
constexpr int WARP_FLOATS = RPW * NBINS;    // 8224
constexpr int CB      = 16;                 // bins per chunk
constexpr int NCHUNK  = 16;                 // 16*16 = bins 0..255 staged
constexpr int STAGES  = 3;
constexpr int SROW    = 17;                 // odd stride: scalar LDS conflict-free
constexpr int STAGE_FLOATS = RPW * SROW;    // 544
constexpr int WPB     = 4;
constexpr int BLOCK   = WPB * 32;

template <int I> using ic = std::integral_constant<int, I>;

// ---------------- compile-time double-precision math ----------------
constexpr double cexp(double x) {
    double s = 1.0, t = 1.0;
    for (int k = 1; k < 60; ++k) { t = t * x / k; s += t; }
    return s;
}
constexpr double cln(double x) {
    int n = 0;
    while (x > 1.3333333333333333) { x *= 0.5; ++n; }
    while (x < 0.75)               { x *= 2.0; --n; }
    double t = (x - 1.0) / (x + 1.0), t2 = t * t, s = 0.0, p = t;
    for (int k = 0; k < 40; ++k) { s += p / (2 * k + 1); p *= t2; }
    return 2.0 * s + n * 0.69314718055994530941723212145818;
}
constexpr double ccos(double x) {
    while (x >  3.14159265358979323846) x -= 6.28318530717958647692528676656;
    while (x < -3.14159265358979323846) x += 6.28318530717958647692528676656;
    double x2 = x * x, s = 1.0, t = 1.0;
    for (int k = 1; k < 30; ++k) { t *= -x2 / ((2.0 * k - 1.0) * (2.0 * k)); s += t; }
    return s;
}
constexpr double csin(double x) {
    double x2 = x * x, s = x, t = x;
    for (int k = 1; k < 30; ++k) { t *= -x2 / ((2.0 * k) * (2.0 * k + 1.0)); s += t; }
    return s;
}

// ---------------- all problem constants, built at compile time ----------------
struct Tables {
    int   chlo[256]; float wlo[256];
    int   chhi[256]; float whi[256];
    float eql[N_CH];
    float Cp[20][ORDER + 1];   // paired cosine coeffs (q=1..20), edges folded into q=1
    float lift[ORDER];
};

constexpr Tables build() {
    Tables T{};
    const double mel_max = 1127.0 * cln(1.0 + 8000.0 / 700.0);
    const double d = mel_max / 41.0;
    double cf[41]{};   for (int s = 0; s < 41; ++s) cf[s] = d * (s + 1);
    double diff[41]{}; diff[0] = cf[0];
    for (int i = 1; i < 41; ++i) diff[i] = cf[i] - cf[i - 1];

    for (int b = 1; b < 256; ++b) {
        const double mel = 1127.0 * cln(1.0 + (31.25 * b) / 700.0);
        int ch = 0;
        for (int s = 0; s < 41; ++s) if (cf[s] < mel) ++ch;   // searchsorted 'left'
        const double w = (cf[ch] - mel) / diff[ch];
        T.chlo[b] = ch - 1;                 T.wlo[b] = (float)w;
        T.chhi[b] = (ch <= 39) ? ch : -1;   T.whi[b] = (float)(1.0 - w);
    }
    T.chlo[0] = -1; T.chhi[0] = -1;
    for (int c = 0; c < N_CH; ++c) {
        const double fhz = 700.0 * (cexp(cf[c] / 1127.0) - 1.0);
        const double f2  = fhz * fhz;
        T.eql[c] = (float)((f2 / (f2 + 160000.0)) * (f2 / (f2 + 160000.0))
                           * (f2 + 1440000.0) / (f2 + 9610000.0));
    }
    // paired cosine transform:
    // r[k] = sum_{q=1..20} Cp[q-1][k] * (k even ? y[q-1]+y[40-q] : y[q-1]-y[40-q])
    for (int q = 1; q <= 20; ++q)
        for (int k = 0; k <= ORDER; ++k) {
            double v = 2.0 * ccos(6.28318530717958647692528676656
                                  * (double)(q * k) / 82.0) / 82.0;
            if (q == 1) v += 1.0 / 82.0;
            T.Cp[q - 1][k] = (float)v;
        }
    for (int m = 1; m <= ORDER; ++m)
        T.lift[m - 1] = (float)(1.0 + 11.0 * csin(3.14159265358979323846 * m / 22.0));
    return T;
}
constexpr Tables TB = build();

// ---------------- compile-time for-loop ----------------
template <int I, int N> struct SF {
    template <class F>
    __device__ __forceinline__ static void run(F&& f) {
        f(ic<I>{});
        SF<I + 1, N>::run((F&&)f);
    }
};
template <int N> struct SF<N, N> {
    template <class F> __device__ __forceinline__ static void run(F&&) {}
};

// cp.async 4B with COMPILE-TIME immediate offsets: SASS LDGSTS [R+imm],[R64+imm]
// -> zero per-copy address arithmetic.
template <int DOFF, int SOFF>
__device__ __forceinline__ void cpa4(unsigned dstBase, const float* srcBase) {
    asm volatile("cp.async.ca.shared.global [%0+%2], [%1+%3], 4;\n"
                 :: "r"(dstBase), "l"(srcBase), "n"(DOFF), "n"(SOFF));
}
__device__ __forceinline__ void cpa_commit() {
    asm volatile("cp.async.commit_group;\n" ::: "memory");
}
template <int N>
__device__ __forceinline__ void cpa_wait() {
    asm volatile("cp.async.wait_group %0;\n" :: "n"(N) : "memory");
}

__global__ void __launch_bounds__(BLOCK, 7)
plp_kernel(const float* __restrict__ x, float* __restrict__ out, int nWarpsTotal) {
    __shared__ float sbuf[WPB][STAGES][STAGE_FLOATS];   // 4*3*2176B = 26112B

    const int lane = threadIdx.x & 31;
    const int wInB = threadIdx.x >> 5;
    const int warpG = blockIdx.x * WPB + wInB;
    if (warpG >= nWarpsTotal) return;

    const float* gw = x + (long long)warpG * WARP_FLOATS;

    const unsigned sb =
        (unsigned)__cvta_generic_to_shared(&sbuf[wInB][0][0]);

    // per-lane constant bases; ALL chunk/row offsets become instruction immediates.
    // copy instr t of a chunk covers rows 2t (lanes 0..15) and 2t+1 (lanes 16..31)
    const int half = lane >> 4;                 // 0/1
    const int colv = lane & 15;                 // column within chunk
    const float* gp = gw + half * NBINS + colv;
    const unsigned sbh = sb + (unsigned)((half * SROW + colv) * 4);

    auto issue_chunk = [&](auto cc2, auto sg2) {
        constexpr int c = cc2.value;
        constexpr int stg = sg2.value;
        SF<0, RPW / 2>::run([&](auto tc) {
            constexpr int t = tc.value;
            cpa4<(stg * STAGE_FLOATS + t * 2 * SROW) * 4,
                 (c * CB + t * 2 * NBINS) * 4>(sbh, gp);
        });
        cpa_commit();
    };

    float fb[N_CH];
    SF<0, N_CH>::run([&](auto c) { fb[c.value] = 0.f; });

    // ---- prologue: 2 chunks in flight ----
    issue_chunk(ic<0>{}, ic<0>{});
    issue_chunk(ic<1>{}, ic<1>{});

    // ---- 16 chunks of 16 bins, 3-stage ring, lookahead 2 ----
    SF<0, NCHUNK>::run([&](auto cc) {
        constexpr int c = cc.value;
        if constexpr (c + 2 < NCHUNK)
            issue_chunk(ic<c + 2>{}, ic<(c + 2) % STAGES>{});
        if constexpr (c + 2 < NCHUNK)      cpa_wait<2>();
        else if constexpr (c + 1 < NCHUNK) cpa_wait<1>();
        else                               cpa_wait<0>();
        __syncwarp();
        const float* xr = &sbuf[wInB][c % STAGES][lane * SROW];
        SF<0, CB>::run([&](auto jc) {
            constexpr int j = jc.value;
            constexpr int b = CB * c + j;
            constexpr int clo = TB.chlo[b];
            constexpr int chi = TB.chhi[b];
            if constexpr (clo >= 0 || chi >= 0) {
                const float xv = xr[j];
                if constexpr (clo >= 0) { constexpr float w = TB.wlo[b]; fb[clo] = fmaf(w, xv, fb[clo]); }
                if constexpr (chi >= 0) { constexpr float w = TB.whi[b]; fb[chi] = fmaf(w, xv, fb[chi]); }
            }
        });
        __syncwarp();   // all lanes done reading before this stage is overwritten
    });

    // ---- equal-loudness + compression (MUFU) ----
    float y[N_CH];
    SF<0, N_CH>::run([&](auto cc_) {
        constexpr int c = cc_.value;
        constexpr float e = TB.eql[c];
        const float v = fmaxf(fb[c], 1e-5f) * e;
        y[c] = __expf(0.33f * __logf(v));
    });

    // ---- autocorrelation via parity-folded cosine transform ----
    float sp[20], sm[20];
    SF<0, 20>::run([&](auto qc) {
        constexpr int q = qc.value;
        sp[q] = y[q] + y[39 - q];
        sm[q] = y[q] - y[39 - q];
    });
    float r[ORDER + 1];
    SF<0, ORDER + 1>::run([&](auto kc) { r[kc.value] = 0.f; });
    SF<0, 20>::run([&](auto qc) {
        constexpr int q = qc.value;
        const float vp = sp[q], vm = sm[q];
        SF<0, ORDER + 1>::run([&](auto kc) {
            constexpr int k = kc.value;
            constexpr float cqk = TB.Cp[q][k];
            r[k] = fmaf(cqk, (k & 1) ? vm : vp, r[k]);
        });
    });

    // ---- Levinson-Durbin (order 16) ----
    float A[ORDER];
    float E = r[0];
    #pragma unroll
    for (int i = 1; i <= ORDER; ++i) {
        float acc = r[i];
        #pragma unroll
        for (int j = 1; j < i; ++j) acc += A[j - 1] * r[i - j];
        const float kk = -__fdividef(acc, E);
        #pragma unroll
        for (int j = 0; j < (i - 1) / 2; ++j) {
            const float t = A[j];
            A[j]         = t + kk * A[i - 2 - j];
            A[i - 2 - j] = A[i - 2 - j] + kk * t;
        }
        if (((i - 1) & 1) == 1) {
            const int mid = (i - 2) / 2;
            A[mid] = A[mid] + kk * A[mid];
        }
        A[i - 1] = kk;
        E = E * (1.0f - kk * kk);
    }

    // ---- LPC -> cepstrum ----
    float cst[ORDER + 1];
    cst[0] = 0.5f * __logf(E);
    #pragma unroll
    for (int m = 1; m <= ORDER; ++m) {
        float acc = A[m - 1];
        #pragma unroll
        for (int k2 = 1; k2 < m; ++k2) {
            const float ratio = (float)k2 / (float)m;
            acc += ratio * cst[k2] * A[m - k2 - 1];
        }
        cst[m] = -acc;
    }

    // ---- lifter + store ----
    float o[ORDER];
    SF<0, ORDER>::run([&](auto icx) {
        constexpr int i = icx.value;
        constexpr float lf = TB.lift[i];
        o[i] = cst[i + 1] * lf;
    });

    const long long row = (long long)warpG * RPW + lane;
    float4* o4 = reinterpret_cast<float4*>(out + row * 16);
    o4[0] = make_float4(o[0],  o[1],  o[2],  o[3]);
    o4[1] = make_float4(o[4],  o[5],  o[6],  o[7]);
    o4[2] = make_float4(o[8],  o[9],  o[10], o[11]);
    o4[3] = make_float4(o[12], o[13], o[14], o[15]);
}

} // namespace plp

extern "C" void kernel_launch(void* const* d_in, const int* in_sizes, int n_in,
                              void* d_out, int out_size) {
    const float* x = (const float*)d_in[0];
    float* out = (float*)d_out;

    const int rows   = in_sizes[0] / plp::NBINS;     // 131072
    const int nWarps = rows / plp::RPW;              // 4096
    const int grid   = (nWarps + plp::WPB - 1) / plp::WPB;  // 1024

    plp::plp_kernel<<<grid, plp::BLOCK>>>(x, out, nWarps);
}

// round 8
// speedup vs baseline: 1.7020x; 1.0643x over previous
#include <cuda_runtime.h>
#include <cstdint>
#include <type_traits>

namespace plp {

constexpr int NBINS = 257;
constexpr int N_CH  = 40;
constexpr int ORDER = 16;
constexpr int RPW   = 32;                     // rows per tile (lane = row)
constexpr int WARP_FLOATS = RPW * NBINS;      // 8224
constexpr int TILE_BYTES  = WARP_FLOATS * 4;  // 32896, multiple of 16

template <int I> using ic = std::integral_constant<int, I>;

// ---------------- compile-time double-precision math ----------------
constexpr double cexp(double x) {
    double s = 1.0, t = 1.0;
    for (int k = 1; k < 60; ++k) { t = t * x / k; s += t; }
    return s;
}
constexpr double cln(double x) {
    int n = 0;
    while (x > 1.3333333333333333) { x *= 0.5; ++n; }
    while (x < 0.75)               { x *= 2.0; --n; }
    double t = (x - 1.0) / (x + 1.0), t2 = t * t, s = 0.0, p = t;
    for (int k = 0; k < 40; ++k) { s += p / (2 * k + 1); p *= t2; }
    return 2.0 * s + n * 0.69314718055994530941723212145818;
}
constexpr double ccos(double x) {
    while (x >  3.14159265358979323846) x -= 6.28318530717958647692528676656;
    while (x < -3.14159265358979323846) x += 6.28318530717958647692528676656;
    double x2 = x * x, s = 1.0, t = 1.0;
    for (int k = 1; k < 30; ++k) { t *= -x2 / ((2.0 * k - 1.0) * (2.0 * k)); s += t; }
    return s;
}
constexpr double csin(double x) {
    double x2 = x * x, s = x, t = x;
    for (int k = 1; k < 30; ++k) { t *= -x2 / ((2.0 * k) * (2.0 * k + 1.0)); s += t; }
    return s;
}

// ---------------- all problem constants, built at compile time ----------------
struct Tables {
    int   chlo[256]; float wlo[256];
    int   chhi[256]; float whi[256];
    float eql[N_CH];
    float Cp[20][ORDER + 1];   // paired cosine coeffs (q=1..20), edges folded into q=1
    float lift[ORDER];
};

constexpr Tables build() {
    Tables T{};
    const double mel_max = 1127.0 * cln(1.0 + 8000.0 / 700.0);
    const double d = mel_max / 41.0;
    double cf[41]{};   for (int s = 0; s < 41; ++s) cf[s] = d * (s + 1);
    double diff[41]{}; diff[0] = cf[0];
    for (int i = 1; i < 41; ++i) diff[i] = cf[i] - cf[i - 1];

    for (int b = 1; b < 256; ++b) {
        const double mel = 1127.0 * cln(1.0 + (31.25 * b) / 700.0);
        int ch = 0;
        for (int s = 0; s < 41; ++s) if (cf[s] < mel) ++ch;   // searchsorted 'left'
        const double w = (cf[ch] - mel) / diff[ch];
        T.chlo[b] = ch - 1;                 T.wlo[b] = (float)w;
        T.chhi[b] = (ch <= 39) ? ch : -1;   T.whi[b] = (float)(1.0 - w);
    }
    T.chlo[0] = -1; T.chhi[0] = -1;
    for (int c = 0; c < N_CH; ++c) {
        const double fhz = 700.0 * (cexp(cf[c] / 1127.0) - 1.0);
        const double f2  = fhz * fhz;
        T.eql[c] = (float)((f2 / (f2 + 160000.0)) * (f2 / (f2 + 160000.0))
                           * (f2 + 1440000.0) / (f2 + 9610000.0));
    }
    // paired cosine transform:
    // r[k] = sum_{q=1..20} Cp[q-1][k] * (k even ? y[q-1]+y[40-q] : y[q-1]-y[40-q])
    for (int q = 1; q <= 20; ++q)
        for (int k = 0; k <= ORDER; ++k) {
            double v = 2.0 * ccos(6.28318530717958647692528676656
                                  * (double)(q * k) / 82.0) / 82.0;
            if (q == 1) v += 1.0 / 82.0;
            T.Cp[q - 1][k] = (float)v;
        }
    for (int m = 1; m <= ORDER; ++m)
        T.lift[m - 1] = (float)(1.0 + 11.0 * csin(3.14159265358979323846 * m / 22.0));
    return T;
}
constexpr Tables TB = build();

// ---------------- compile-time for-loop ----------------
template <int I, int N> struct SF {
    template <class F>
    __device__ __forceinline__ static void run(F&& f) {
        f(ic<I>{});
        SF<I + 1, N>::run((F&&)f);
    }
};
template <int N> struct SF<N, N> {
    template <class F> __device__ __forceinline__ static void run(F&&) {}
};

__device__ __forceinline__ void mbar_init(unsigned bar, unsigned cnt) {
    asm volatile("mbarrier.init.shared.b64 [%0], %1;" :: "r"(bar), "r"(cnt) : "memory");
}
__device__ __forceinline__ void fence_async_shared() {
    asm volatile("fence.proxy.async.shared::cta;" ::: "memory");
}
__device__ __forceinline__ void mbar_expect_tx(unsigned bar, unsigned bytes) {
    asm volatile("mbarrier.arrive.expect_tx.shared.b64 _, [%0], %1;"
                 :: "r"(bar), "r"(bytes) : "memory");
}
__device__ __forceinline__ void bulk_g2s(unsigned dst, const void* src,
                                         unsigned bytes, unsigned bar) {
    asm volatile(
        "cp.async.bulk.shared::cta.global.mbarrier::complete_tx::bytes "
        "[%0], [%1], %2, [%3];"
        :: "r"(dst), "l"(src), "r"(bytes), "r"(bar) : "memory");
}
__device__ __forceinline__ void mbar_wait(unsigned bar, unsigned parity) {
    asm volatile(
        "{\n\t"
        ".reg .pred P;\n"
        "WAIT_%=:\n\t"
        "mbarrier.try_wait.parity.acquire.cta.shared::cta.b64 P, [%0], %1, 0x989680;\n\t"
        "@P bra.uni DONE_%=;\n\t"
        "bra.uni WAIT_%=;\n"
        "DONE_%=:\n\t"
        "}"
        :: "r"(bar), "r"(parity) : "memory");
}

__global__ void __launch_bounds__(32)
plp_kernel(const float* __restrict__ x, float* __restrict__ out) {
    __shared__ __align__(128) float xs[WARP_FLOATS];   // 32896 B flat tile
    __shared__ __align__(8)   unsigned long long mbar;

    const int lane = threadIdx.x;
    const long long tile = blockIdx.x;

    const unsigned sdst = (unsigned)__cvta_generic_to_shared(xs);
    const unsigned sbar = (unsigned)__cvta_generic_to_shared(&mbar);

    // ---- one TMA bulk copy for the whole 32-row tile ----
    if (lane == 0) {
        mbar_init(sbar, 1);
        fence_async_shared();
        mbar_expect_tx(sbar, TILE_BYTES);
        bulk_g2s(sdst, x + tile * WARP_FLOATS, TILE_BYTES, sbar);
    }
    __syncwarp();
    mbar_wait(sbar, 0);

    // ---- each lane owns one row; stride 257 (odd) => bank-conflict-free ----
    const float* xr = xs + lane * NBINS;

    float fb[N_CH];
    SF<0, N_CH>::run([&](auto c) { fb[c.value] = 0.f; });

    // triangular mel filterbank, weights as FFMA immediates
    SF<1, 256>::run([&](auto bc) {
        constexpr int b = bc.value;
        constexpr int clo = TB.chlo[b];
        constexpr int chi = TB.chhi[b];
        if constexpr (clo >= 0 || chi >= 0) {
            const float xv = xr[b];
            if constexpr (clo >= 0) { constexpr float w = TB.wlo[b]; fb[clo] = fmaf(w, xv, fb[clo]); }
            if constexpr (chi >= 0) { constexpr float w = TB.whi[b]; fb[chi] = fmaf(w, xv, fb[chi]); }
        }
    });

    // ---- equal-loudness + compression (MUFU) ----
    float y[N_CH];
    SF<0, N_CH>::run([&](auto cc_) {
        constexpr int c = cc_.value;
        constexpr float e = TB.eql[c];
        const float v = fmaxf(fb[c], 1e-5f) * e;
        y[c] = __expf(0.33f * __logf(v));
    });

    // ---- autocorrelation via parity-folded cosine transform ----
    float sp[20], sm[20];
    SF<0, 20>::run([&](auto qc) {
        constexpr int q = qc.value;
        sp[q] = y[q] + y[39 - q];
        sm[q] = y[q] - y[39 - q];
    });
    float r[ORDER + 1];
    SF<0, ORDER + 1>::run([&](auto kc) { r[kc.value] = 0.f; });
    SF<0, 20>::run([&](auto qc) {
        constexpr int q = qc.value;
        const float vp = sp[q], vm = sm[q];
        SF<0, ORDER + 1>::run([&](auto kc) {
            constexpr int k = kc.value;
            constexpr float cqk = TB.Cp[q][k];
            r[k] = fmaf(cqk, (k & 1) ? vm : vp, r[k]);
        });
    });

    // ---- Levinson-Durbin (order 16) ----
    float A[ORDER];
    float E = r[0];
    #pragma unroll
    for (int i = 1; i <= ORDER; ++i) {
        float acc = r[i];
        #pragma unroll
        for (int j = 1; j < i; ++j) acc += A[j - 1] * r[i - j];
        const float kk = -__fdividef(acc, E);
        #pragma unroll
        for (int j = 0; j < (i - 1) / 2; ++j) {
            const float t = A[j];
            A[j]         = t + kk * A[i - 2 - j];
            A[i - 2 - j] = A[i - 2 - j] + kk * t;
        }
        if (((i - 1) & 1) == 1) {
            const int mid = (i - 2) / 2;
            A[mid] = A[mid] + kk * A[mid];
        }
        A[i - 1] = kk;
        E = E * (1.0f - kk * kk);
    }

    // ---- LPC -> cepstrum ----
    float cst[ORDER + 1];
    cst[0] = 0.5f * __logf(E);
    #pragma unroll
    for (int m = 1; m <= ORDER; ++m) {
        float acc = A[m - 1];
        #pragma unroll
        for (int k2 = 1; k2 < m; ++k2) {
            const float ratio = (float)k2 / (float)m;
            acc += ratio * cst[k2] * A[m - k2 - 1];
        }
        cst[m] = -acc;
    }

    // ---- lifter + store (warp writes 2KB contiguous) ----
    float o[ORDER];
    SF<0, ORDER>::run([&](auto icx) {
        constexpr int i = icx.value;
        constexpr float lf = TB.lift[i];
        o[i] = cst[i + 1] * lf;
    });

    const long long row = tile * RPW + lane;
    float4* o4 = reinterpret_cast<float4*>(out + row * 16);
    o4[0] = make_float4(o[0],  o[1],  o[2],  o[3]);
    o4[1] = make_float4(o[4],  o[5],  o[6],  o[7]);
    o4[2] = make_float4(o[8],  o[9],  o[10], o[11]);
    o4[3] = make_float4(o[12], o[13], o[14], o[15]);
}

} // namespace plp

extern "C" void kernel_launch(void* const* d_in, const int* in_sizes, int n_in,
                              void* d_out, int out_size) {
    const float* x = (const float*)d_in[0];
    float* out = (float*)d_out;

    const int rows   = in_sizes[0] / plp::NBINS;   // 131072
    const int nTiles = rows / plp::RPW;            // 4096 blocks, 1 tile each

    plp::plp_kernel<<<nTiles, 32>>>(x, out);
}